// round 16
// baseline (speedup 1.0000x reference)
#include <cuda_runtime.h>
#include <cstdint>

#define NV   64
#define HQ   252            // quads per half-batch stage
#define F4S  756            // float4 per half-batch stage
#define F4B  1512           // float4 per batch
#define TPB  256
#define MAXB 8              // max batches per CTA (ceil(4096/592)=7)

__global__ __launch_bounds__(TPB, 4) void score_kernel(
    const float* __restrict__ views,     // [B, 64, 7]
    const float* __restrict__ pairs,     // [B, 2016, 3]
    const float* __restrict__ s_a1,
    const float* __restrict__ s_a2,
    const float* __restrict__ s_gsd,
    const float* __restrict__ s_scale,
    const float* __restrict__ s_nrm,
    const float* __restrict__ s_dist,
    float* __restrict__ out,             // [B]
    int B)
{
    __shared__ float w[MAXB][NV];
    __shared__ float warpsum[MAXB][TPB / 32];

    const int tid = threadIdx.x;
    const int bx  = blockIdx.x;
    const int gsz = gridDim.x;

    int nb = (B - bx + gsz - 1) / gsz;
    if (nb > MAXB) nb = MAXB;

    // ---- per-thread pair slot (shared by all batches) ----
    const int qt = (tid < HQ) ? tid : 0;
    const float vm = (tid < HQ) ? 1.0f : 0.0f;
    const float4* pbase = (const float4*)pairs + 3 * qt;

    // address of half-group (half=0 even, 1 odd) of batch t, clamped to valid
    #define GADDR(t_, half_) \
        (pbase + (size_t)(bx + (((t_) < nb) ? (t_) : (nb - 1)) * gsz) * F4B \
               + (half_) * F4S)

    #define LOADG(d0, d1, d2, t_, half_)                                       \
    {                                                                          \
        const float4* p_ = GADDR(t_, half_);                                   \
        d0 = p_[0]; d1 = p_[1]; d2 = p_[2];                                    \
    }

    // ---- fire 3 half-stage load groups immediately (depth-2 pipeline) ----
    float4 C0, C1, C2, A0, A1, A2, Bf0, Bf1, Bf2;
    LOADG(C0, C1, C2, 0, 0);     // even half, batch 0  (consumed first)
    LOADG(A0, A1, A2, 0, 1);     // odd  half, batch 0
    LOADG(Bf0, Bf1, Bf2, 1, 0);  // even half, batch 1

    // ---- scalar params ----
    const float L2E = 1.4426950408889634f;
    const float a1 = *s_a1;
    const float a2 = *s_a2;
    const float c_a1 = -0.5f * L2E / (a1 * a1);
    const float c_a2 = -0.5f * L2E / (a2 * a2);
    const float sc = *s_scale;
    const float c_sc = -0.5f * L2E / (sc * sc);
    const float TH = 20.0f / 90.0f;

    // ---- per-view weights for all owned batches (overlap in-flight loads) --
    {
        const float gs = *s_gsd;   const float c_gsd  = -0.5f * L2E / (gs * gs);
        const float ns = *s_nrm;   const float c_nrm  = -0.5f * L2E / (ns * ns);
        const float ds = *s_dist;  const float c_dist = -0.5f * L2E / (ds * ds);
        for (int e = tid; e < nb * NV; e += TPB) {
            int t = e >> 6;
            int v = e & 63;
            const float* vr = views + ((size_t)(bx + t * gsz) * NV + v) * 7;
            float v0 = vr[0];
            float x4 = vr[4];
            float x5 = vr[5];
            float x6 = vr[6];
            float m  = (v0 == 1.0f) ? 1.0f : 0.0f;
            float x4sq = x4 * x4;
            float arg = fmaf(x4sq * x4sq, c_gsd,
                        fmaf(x5 * x5,     c_nrm,
                             (x6 * x6) *  c_dist));
            w[t][v] = m * exp2f(arg);
        }
    }

    // ---- (i,j) decode: once per CTA, both half-stage offsets ----
    int i0, j0, i1, j1;
    {
        int p = 4 * qt;
        int i = (int)((127.0f - sqrtf((float)(16129 - 8 * p))) * 0.5f);
        while (p < ((i * (127 - i)) >> 1)) --i;
        while (p >= (((i + 1) * (126 - i)) >> 1)) ++i;
        i0 = i; j0 = p - ((i * (127 - i)) >> 1) + i + 1;
    }
    {
        int p = 4 * (qt + HQ);
        int i = (int)((127.0f - sqrtf((float)(16129 - 8 * p))) * 0.5f);
        while (p < ((i * (127 - i)) >> 1)) --i;
        while (p >= (((i + 1) * (126 - i)) >> 1)) ++i;
        i1 = i; j1 = p - ((i * (127 - i)) >> 1) + i + 1;
    }

    __syncthreads();   // w[] visible

    // extracted current-stage scalars (frees the source float4 registers)
    float pmE[4], avE[4], svE[4];

    #define EXTRACT(f0, f1, f2)                                                \
    {                                                                          \
        pmE[0] = ((f0).x != 0.0f) ? vm : 0.0f;                                 \
        pmE[1] = ((f0).w != 0.0f) ? vm : 0.0f;                                 \
        pmE[2] = ((f1).z != 0.0f) ? vm : 0.0f;                                 \
        pmE[3] = ((f2).y != 0.0f) ? vm : 0.0f;                                 \
        avE[0] = (f0).y; avE[1] = (f1).x; avE[2] = (f1).w; avE[3] = (f2).z;    \
        svE[0] = (f0).z; svE[1] = (f1).y; svE[2] = (f2).x; svE[3] = (f2).w;    \
    }

    #define PROC_E(istart, jstart, wrow)                                       \
    {                                                                          \
        int i = (istart), j = (jstart);                                        \
        _Pragma("unroll")                                                      \
        for (int k = 0; k < 4; ++k) {                                          \
            float a = avE[k];                                                  \
            float sx = svE[k];                                                 \
            float m = (a == TH) ? 0.0f : pmE[k];                               \
            float ca = (a < TH) ? c_a1 : c_a2;                                 \
            float arg = fmaf(a * a, ca, (sx * sx) * c_sc);                     \
            float e = exp2f(arg);                                              \
            acc = fmaf(m * e, (wrow)[i] * (wrow)[j], acc);                     \
            ++j;                                                               \
            if (j == NV) { ++i; j = i + 1; }                                   \
        }                                                                      \
    }

    float acc = 0.0f;
    EXTRACT(C0, C1, C2);   // stage "even 0" into scalars; C regs now free

    // ---- mainloop invariant at top of iteration t:
    //      E = even half of t (extracted), A = odd t (in flight),
    //      B = even t+1 (in flight) ----
    for (int t = 0; t < nb; ++t) {
        PROC_E(i0, j0, w[t]);                    // even half of batch t

        EXTRACT(A0, A1, A2);                     // odd t -> scalars
        LOADG(A0, A1, A2, t + 1, 1);             // refill A: odd t+1

        PROC_E(i1, j1, w[t]);                    // odd half of batch t

        // batch t done: stash warp partials (distinct slots, no sync needed)
        {
            float a = acc;
            #pragma unroll
            for (int o = 16; o > 0; o >>= 1)
                a += __shfl_down_sync(0xffffffffu, a, o);
            if ((tid & 31) == 0) warpsum[t][tid >> 5] = a;
            acc = 0.0f;
        }

        EXTRACT(Bf0, Bf1, Bf2);                  // even t+1 -> scalars
        LOADG(Bf0, Bf1, Bf2, t + 2, 0);          // refill B: even t+2
    }
    #undef PROC_E
    #undef EXTRACT
    #undef LOADG
    #undef GADDR

    __syncthreads();   // warpsum visible

    // ---- fused epilogue: reduce up to 8 batches x 8 warp-partials ----
    if (tid < 64) {
        const int bb = tid >> 3;
        const int k  = tid & 7;
        float p = (bb < nb) ? warpsum[bb][k] : 0.0f;
        p += __shfl_down_sync(0xffffffffu, p, 4);
        p += __shfl_down_sync(0xffffffffu, p, 2);
        p += __shfl_down_sync(0xffffffffu, p, 1);
        if (k == 0 && bb < nb) out[bx + bb * gsz] = p;
    }
}

extern "C" void kernel_launch(void* const* d_in, const int* in_sizes, int n_in,
                              void* d_out, int out_size) {
    const float* views  = (const float*)d_in[0];
    const float* pairs  = (const float*)d_in[1];
    // d_in[2] = point_attribute (unused by reference computation)
    const float* a1     = (const float*)d_in[3];
    const float* a2     = (const float*)d_in[4];
    const float* gsd    = (const float*)d_in[5];
    const float* scale  = (const float*)d_in[6];
    const float* nrm    = (const float*)d_in[7];
    const float* dist   = (const float*)d_in[8];
    float* out = (float*)d_out;

    int B = in_sizes[0] / (NV * 7);
    int grid = 592;                       // 148 SMs x 4 resident CTAs, 1 wave
    if (grid > B) grid = B;

    score_kernel<<<grid, TPB>>>(views, pairs, a1, a2, gsd, scale, nrm, dist,
                                out, B);
}